// round 15
// baseline (speedup 1.0000x reference)
#include <cuda_runtime.h>
#include <math.h>

#define NN 100000
#define NE 1000000
#define IN_CH 64
#define HID 128
#define NG 256

#define SCAN_BLOCKS 128
#define SCAN_CH ((NN + SCAN_BLOCKS - 1) / SCAN_BLOCKS)   // 782
#define CSR_BLOCKS 148
#define CSR_THREADS (CSR_BLOCKS * 256)

// ---------------- scratch (device globals; no allocation) ----------------
__device__ int g_idx64;              // 1 if indices are int64, 0 if int32
__device__ int g_cnt[NN];
__device__ int g_row[NN];
__device__ int g_cur[NN];
__device__ float g_invdeg[NN];
__device__ int g_srcs[NE];
__device__ int g_blocksum[SCAN_BLOCKS];
__device__ unsigned g_bar_count;     // grid barrier arrive counter (returns to 0)
__device__ unsigned g_bar_gen;       // grid barrier generation (monotonic)
__device__ __align__(16) float g_agg1[NN * IN_CH];   // 25.6 MB
__device__ __align__(16) float g_agg2[NN * HID];     // 51.2 MB
__device__ __align__(16) float g_h1[NN * HID];       // 51.2 MB
__device__ float g_pooled[NG * HID];
// pre-split weights: packed bf16x2 pairs along k, [outch][K/2]
__device__ __align__(16) unsigned g_Wh1[HID * IN_CH];    // K=128 -> 64 pairs
__device__ __align__(16) unsigned g_Wl1[HID * IN_CH];
__device__ __align__(16) unsigned g_Wh2[HID * HID];      // K=256 -> 128 pairs
__device__ __align__(16) unsigned g_Wl2[HID * HID];

// index accessor honoring detected dtype
__device__ __forceinline__ int getidx(const void* p, long long i) {
    if (g_idx64) return (int)((const long long*)p)[i];
    return ((const int*)p)[i];
}

// ---------------- manual grid barrier (all CSR_BLOCKS co-resident) ----------------
__device__ __forceinline__ void grid_sync() {
    __threadfence();
    __syncthreads();
    if (threadIdx.x == 0) {
        unsigned gen = atomicAdd(&g_bar_gen, 0u);   // L2 read
        unsigned arr = atomicAdd(&g_bar_count, 1u);
        if (arr == (unsigned)CSR_BLOCKS - 1u) {
            atomicExch(&g_bar_count, 0u);           // reset BEFORE release
            atomicAdd(&g_bar_gen, 1u);              // release
        } else {
            while (atomicAdd(&g_bar_gen, 0u) == gen) {}
        }
    }
    __syncthreads();
    __threadfence();
}

// ---------------- bf16 helpers ----------------
__device__ __forceinline__ unsigned pack_bf16x2(float lo, float hi) {
    unsigned r;
    asm("cvt.rn.bf16x2.f32 %0, %1, %2;" : "=r"(r) : "f"(hi), "f"(lo));
    return r;
}

__device__ __forceinline__ void mma_bf16(float* c, const unsigned* a, const unsigned* b) {
    asm volatile(
        "mma.sync.aligned.m16n8k16.row.col.f32.bf16.bf16.f32 "
        "{%0,%1,%2,%3},{%4,%5,%6,%7},{%8,%9},{%0,%1,%2,%3};"
        : "+f"(c[0]), "+f"(c[1]), "+f"(c[2]), "+f"(c[3])
        : "r"(a[0]), "r"(a[1]), "r"(a[2]), "r"(a[3]), "r"(b[0]), "r"(b[1]));
}

__device__ __forceinline__ void ldsm_x4(unsigned& r0, unsigned& r1, unsigned& r2, unsigned& r3,
                                        unsigned addr) {
    asm volatile("ldmatrix.sync.aligned.m8n8.x4.shared.b16 {%0,%1,%2,%3}, [%4];"
                 : "=r"(r0), "=r"(r1), "=r"(r2), "=r"(r3) : "r"(addr));
}

__device__ __forceinline__ void ldsm_x2(unsigned& r0, unsigned& r1, unsigned addr) {
    asm volatile("ldmatrix.sync.aligned.m8n8.x2.shared.b16 {%0,%1}, [%2];"
                 : "=r"(r0), "=r"(r1) : "r"(addr));
}

// convert 8 consecutive floats into 4 packed hi-words + 4 packed lo-words
__device__ __forceinline__ void split_bf16_8(const float* v, unsigned* hp, unsigned* lp) {
#pragma unroll
    for (int j = 0; j < 4; j++) {
        float a0 = v[2 * j], a1 = v[2 * j + 1];
        unsigned h = pack_bf16x2(a0, a1);
        float h0 = __uint_as_float(h << 16);
        float h1 = __uint_as_float(h & 0xffff0000u);
        hp[j] = h;
        lp[j] = pack_bf16x2(a0 - h0, a1 - h1);
    }
}

// ---------------- fused CSR build: probe+zero+wsplit | hist | sums | scan | fill ----------------
__global__ void __launch_bounds__(256) build_csr(
    const unsigned long long* __restrict__ ei64, const void* __restrict__ ei,
    const float* __restrict__ Wl1, const float* __restrict__ Wr1,
    const float* __restrict__ Wl2, const float* __restrict__ Wr2) {
    __shared__ int sb[256];
    __shared__ int s_off;
    int b = blockIdx.x, t = threadIdx.x;
    int gtid = b * 256 + t;
    const int gstride = CSR_THREADS;

    // ---- phase 0: dtype probe, zero counters/pooled, weight split ----
    if (gtid == 0) {
        int is64 = 1;
        for (int i = 0; i < 16; i++)
            if (ei64[i] >> 32) is64 = 0;
        g_idx64 = is64;
    }
    for (int j = gtid; j < NN; j += gstride) g_cnt[j] = 0;
    for (int j = gtid; j < NG * HID; j += gstride) g_pooled[j] = 0.f;
    {
        const int P1 = HID * IN_CH;
        const int P2 = HID * HID;
        for (int idx = gtid; idx < P1 + P2; idx += gstride) {
            if (idx < P1) {
                const int PPR = IN_CH;
                int row = idx / PPR, p = idx % PPR;
                int k0 = 2 * p;
                const int KH = IN_CH;
                float v0 = (k0 < KH) ? Wl1[row * KH + k0] : Wr1[row * KH + k0 - KH];
                float v1 = (k0 < KH) ? Wl1[row * KH + k0 + 1] : Wr1[row * KH + k0 + 1 - KH];
                unsigned h = pack_bf16x2(v0, v1);
                float h0 = __uint_as_float(h << 16);
                float h1 = __uint_as_float(h & 0xffff0000u);
                g_Wh1[idx] = h;
                g_Wl1[idx] = pack_bf16x2(v0 - h0, v1 - h1);
            } else {
                int j = idx - P1;
                const int PPR = HID;
                int row = j / PPR, p = j % PPR;
                int k0 = 2 * p;
                const int KH = HID;
                float v0 = (k0 < KH) ? Wl2[row * KH + k0] : Wr2[row * KH + k0 - KH];
                float v1 = (k0 < KH) ? Wl2[row * KH + k0 + 1] : Wr2[row * KH + k0 + 1 - KH];
                unsigned h = pack_bf16x2(v0, v1);
                float h0 = __uint_as_float(h << 16);
                float h1 = __uint_as_float(h & 0xffff0000u);
                g_Wh2[j] = h;
                g_Wl2[j] = pack_bf16x2(v0 - h0, v1 - h1);
            }
        }
    }
    grid_sync();

    // ---- phase 1: histogram of dst degrees ----
    for (int e = gtid; e < NE; e += gstride)
        atomicAdd(&g_cnt[getidx(ei, NE + e)], 1);
    grid_sync();

    // ---- phase 2: per-chunk sums (blocks 0..SCAN_BLOCKS-1) ----
    if (b < SCAN_BLOCKS) {
        int base = b * SCAN_CH;
        int end = min(base + SCAN_CH, NN);
        int s = 0;
        for (int idx = base + t; idx < end; idx += 256) s += g_cnt[idx];
        sb[t] = s;
        __syncthreads();
        for (int off = 128; off > 0; off >>= 1) {
            if (t < off) sb[t] += sb[t + off];
            __syncthreads();
        }
        if (t == 0) g_blocksum[b] = sb[0];
    }
    grid_sync();

    // ---- phase 3: exclusive scan, write row/cur/invdeg ----
    if (b < SCAN_BLOCKS) {
        int base = b * SCAN_CH;
        int end = min(base + SCAN_CH, NN);
        sb[t] = (t < b) ? g_blocksum[t] : 0;
        __syncthreads();
        for (int off = 128; off > 0; off >>= 1) {
            if (t < off) sb[t] += sb[t + off];
            __syncthreads();
        }
        if (t == 0) s_off = sb[0];
        __syncthreads();
        for (int tile = base; tile < end; tile += 256) {
            int idx = tile + t;
            int c = (idx < end) ? g_cnt[idx] : 0;
            sb[t] = c;
            __syncthreads();
            for (int off = 1; off < 256; off <<= 1) {
                int u = (t >= off) ? sb[t - off] : 0;
                __syncthreads();
                sb[t] += u;
                __syncthreads();
            }
            int incl = sb[t];
            int excl = incl - c;
            if (idx < end) {
                int r = s_off + excl;
                g_row[idx] = r;
                g_cur[idx] = r;
                g_invdeg[idx] = 1.0f / fmaxf((float)c, 1.0f);
            }
            __syncthreads();
            if (t == 255) s_off += sb[255];
            __syncthreads();
        }
    }
    grid_sync();

    // ---- phase 4: fill CSR src lists ----
    for (int e = gtid; e < NE; e += gstride) {
        int dst = getidx(ei, NE + e);
        int src = getidx(ei, e);
        int pos = atomicAdd(&g_cur[dst], 1);
        g_srcs[pos] = src;
    }
}

// ---------------- gather-mean layer 1 (64 ch), 4-way unrolled ----------------
__global__ void __launch_bounds__(256) gather1(const float4* __restrict__ x4) {
    unsigned t = blockIdx.x * blockDim.x + threadIdx.x;
    unsigned n = t >> 4, q = t & 15;
    if (n >= NN) return;
    int start = g_row[n];
    int cnt = g_cnt[n];
    float inv = g_invdeg[n];
    float4 acc = make_float4(0.f, 0.f, 0.f, 0.f);
    int j = 0;
    for (; j + 3 < cnt; j += 4) {
        int s0 = g_srcs[start + j];
        int s1 = g_srcs[start + j + 1];
        int s2 = g_srcs[start + j + 2];
        int s3 = g_srcs[start + j + 3];
        float4 v0 = x4[(size_t)s0 * 16 + q];
        float4 v1 = x4[(size_t)s1 * 16 + q];
        float4 v2 = x4[(size_t)s2 * 16 + q];
        float4 v3 = x4[(size_t)s3 * 16 + q];
        acc.x += v0.x + v1.x + v2.x + v3.x;
        acc.y += v0.y + v1.y + v2.y + v3.y;
        acc.z += v0.z + v1.z + v2.z + v3.z;
        acc.w += v0.w + v1.w + v2.w + v3.w;
    }
    for (; j < cnt; j++) {
        int s = g_srcs[start + j];
        float4 v = x4[(size_t)s * 16 + q];
        acc.x += v.x; acc.y += v.y; acc.z += v.z; acc.w += v.w;
    }
    acc.x *= inv; acc.y *= inv; acc.z *= inv; acc.w *= inv;
    ((float4*)g_agg1)[(size_t)n * 16 + q] = acc;
}

// ---------------- gather-mean layer 2 (128 ch), 4-way unrolled ----------------
__global__ void __launch_bounds__(256) gather2() {
    unsigned t = blockIdx.x * blockDim.x + threadIdx.x;
    unsigned n = t >> 5, q = t & 31;
    if (n >= NN) return;
    int start = g_row[n];
    int cnt = g_cnt[n];
    float inv = g_invdeg[n];
    const float4* h4 = (const float4*)g_h1;
    float4 acc = make_float4(0.f, 0.f, 0.f, 0.f);
    int j = 0;
    for (; j + 3 < cnt; j += 4) {
        int s0 = g_srcs[start + j];
        int s1 = g_srcs[start + j + 1];
        int s2 = g_srcs[start + j + 2];
        int s3 = g_srcs[start + j + 3];
        float4 v0 = h4[(size_t)s0 * 32 + q];
        float4 v1 = h4[(size_t)s1 * 32 + q];
        float4 v2 = h4[(size_t)s2 * 32 + q];
        float4 v3 = h4[(size_t)s3 * 32 + q];
        acc.x += v0.x + v1.x + v2.x + v3.x;
        acc.y += v0.y + v1.y + v2.y + v3.y;
        acc.z += v0.z + v1.z + v2.z + v3.z;
        acc.w += v0.w + v1.w + v2.w + v3.w;
    }
    for (; j < cnt; j++) {
        int s = g_srcs[start + j];
        float4 v = h4[(size_t)s * 32 + q];
        acc.x += v.x; acc.y += v.y; acc.z += v.z; acc.w += v.w;
    }
    acc.x *= inv; acc.y *= inv; acc.z *= inv; acc.w *= inv;
    ((float4*)g_agg2)[(size_t)n * 32 + q] = acc;
}

// ---------------- tensor-core fused SAGE GEMM (3xBF16 m16n8k16 + ldmatrix) ----------------
// out[n, c] = relu( agg[n] @ W0^T + feat[n] @ W1^T + bias )   (agg pre-normalized)
// Block tile: 128 nodes x 128 ch, 256 threads = 8 warps (4 M x 2 N).
// Single 24 KB smem buffer (occupancy-sensitive: do NOT double-buffer).
template <int K, bool DO_POOL>
__device__ __forceinline__ void tc_gemm_body(
    const float* __restrict__ agg, const float* __restrict__ feat,
    const unsigned* __restrict__ Wh, const unsigned* __restrict__ Wl,
    const float* __restrict__ bias, float* __restrict__ out,
    const void* __restrict__ batch) {
    constexpr int KH = K / 2;
    constexpr int PPR = K / 2;           // weight pairs per row
    __shared__ unsigned Ah[128][12], Al[128][12];   // [row][kpair], 48B stride
    __shared__ unsigned Bh[128][12], Bl[128][12];   // [outch][kpair]

    int tid = threadIdx.x;
    int lane = tid & 31, wid = tid >> 5;
    int warpM = wid & 3, warpN = wid >> 2;
    int g = lane >> 2, c = lane & 3;
    int m0 = blockIdx.x * 128;

    int lrow = tid >> 1;             // 0..127
    int lhalf = (tid & 1) * 8;       // float offset 0 or 8
    int lkp = (tid & 1) * 4;         // kpair offset 0 or 4

    // ---- ldmatrix addresses (constant across tiles) ----
    unsigned AhB = (unsigned)__cvta_generic_to_shared(&Ah[0][0]);
    unsigned AlB = (unsigned)__cvta_generic_to_shared(&Al[0][0]);
    unsigned BhB = (unsigned)__cvta_generic_to_shared(&Bh[0][0]);
    unsigned BlB = (unsigned)__cvta_generic_to_shared(&Bl[0][0]);
    int arow = (lane & 7) + (lane & 8);          // row within m16 tile
    unsigned acol = (lane & 16) ? 16u : 0u;      // k-half byte offset
    unsigned aoff0 = (unsigned)(warpM * 32 + arow) * 48u + acol;
    unsigned aoff1 = aoff0 + 16u * 48u;          // second m16 tile
    unsigned boff = (unsigned)(warpN * 64 + (lane & 7)) * 48u + ((lane & 8) ? 16u : 0u);

    float acc[2][8][4];
#pragma unroll
    for (int mt = 0; mt < 2; mt++)
#pragma unroll
        for (int nt = 0; nt < 8; nt++)
#pragma unroll
            for (int i = 0; i < 4; i++) acc[mt][nt][i] = 0.f;

    int node_l = m0 + lrow;
    bool av = node_l < NN;

    float a_reg[8];
    uint4 wh_reg, wl_reg;
    // ---- load tile 0 into registers ----
    {
        int kg = lhalf;
        float4 v0 = make_float4(0.f, 0.f, 0.f, 0.f), v1 = v0;
        if (av) {
            const float* base = (kg < KH) ? (agg + (size_t)node_l * KH + kg)
                                          : (feat + (size_t)node_l * KH + (kg - KH));
            v0 = *(const float4*)base;
            v1 = *(const float4*)(base + 4);
        }
        a_reg[0] = v0.x; a_reg[1] = v0.y; a_reg[2] = v0.z; a_reg[3] = v0.w;
        a_reg[4] = v1.x; a_reg[5] = v1.y; a_reg[6] = v1.z; a_reg[7] = v1.w;
        wh_reg = *(const uint4*)(Wh + (size_t)lrow * PPR + lkp);
        wl_reg = *(const uint4*)(Wl + (size_t)lrow * PPR + lkp);
    }

    for (int kk = 0; kk < K; kk += 16) {
        // ---- convert A regs -> packed bf16 hi/lo; store B regs directly ----
        {
            unsigned hp[4], lp[4];
            split_bf16_8(a_reg, hp, lp);
            *(uint4*)&Ah[lrow][lkp] = make_uint4(hp[0], hp[1], hp[2], hp[3]);
            *(uint4*)&Al[lrow][lkp] = make_uint4(lp[0], lp[1], lp[2], lp[3]);
            *(uint4*)&Bh[lrow][lkp] = wh_reg;
            *(uint4*)&Bl[lrow][lkp] = wl_reg;
        }
        __syncthreads();

        // ---- prefetch next tile into registers ----
        if (kk + 16 < K) {
            int kg = kk + 16 + lhalf;
            float4 v0 = make_float4(0.f, 0.f, 0.f, 0.f), v1 = v0;
            if (av) {
                const float* base = (kg < KH) ? (agg + (size_t)node_l * KH + kg)
                                              : (feat + (size_t)node_l * KH + (kg - KH));
                v0 = *(const float4*)base;
                v1 = *(const float4*)(base + 4);
            }
            a_reg[0] = v0.x; a_reg[1] = v0.y; a_reg[2] = v0.z; a_reg[3] = v0.w;
            a_reg[4] = v1.x; a_reg[5] = v1.y; a_reg[6] = v1.z; a_reg[7] = v1.w;
            int pbase = (kk + 16) / 2 + lkp;
            wh_reg = *(const uint4*)(Wh + (size_t)lrow * PPR + pbase);
            wl_reg = *(const uint4*)(Wl + (size_t)lrow * PPR + pbase);
        }

        // ---- compute: ldmatrix fragment loads + MMA ----
        {
            unsigned ah[2][4], al[2][4];
            ldsm_x4(ah[0][0], ah[0][1], ah[0][2], ah[0][3], AhB + aoff0);
            ldsm_x4(ah[1][0], ah[1][1], ah[1][2], ah[1][3], AhB + aoff1);
            ldsm_x4(al[0][0], al[0][1], al[0][2], al[0][3], AlB + aoff0);
            ldsm_x4(al[1][0], al[1][1], al[1][2], al[1][3], AlB + aoff1);
#pragma unroll
            for (int nt = 0; nt < 8; nt++) {
                unsigned bh[2], bl[2];
                ldsm_x2(bh[0], bh[1], BhB + boff + nt * 384u);
                ldsm_x2(bl[0], bl[1], BlB + boff + nt * 384u);
#pragma unroll
                for (int mt = 0; mt < 2; mt++) {
                    mma_bf16(acc[mt][nt], ah[mt], bh);   // hi*hi
                    mma_bf16(acc[mt][nt], ah[mt], bl);   // hi*lo
                    mma_bf16(acc[mt][nt], al[mt], bh);   // lo*hi
                }
            }
        }
        __syncthreads();
    }

    // ---- epilogue ----
    if (DO_POOL) {
        int lastrow = min(m0 + 127, NN - 1);
        int g0 = getidx(batch, m0);
        int g1 = getidx(batch, lastrow);
        if (g1 - g0 <= 1) {
            float sumA[16], sumB[16];
#pragma unroll
            for (int k = 0; k < 16; k++) { sumA[k] = 0.f; sumB[k] = 0.f; }
#pragma unroll
            for (int mt = 0; mt < 2; mt++) {
                int r0 = m0 + warpM * 32 + mt * 16 + g;
                int r1 = r0 + 8;
                int gr0 = (r0 < NN) ? getidx(batch, r0) : -1;
                int gr1 = (r1 < NN) ? getidx(batch, r1) : -1;
#pragma unroll
                for (int nt = 0; nt < 8; nt++) {
                    int col = warpN * 64 + nt * 8 + 2 * c;
                    float b0 = bias[col], b1 = bias[col + 1];
                    float v00 = fmaxf(acc[mt][nt][0] + b0, 0.f);
                    float v01 = fmaxf(acc[mt][nt][1] + b1, 0.f);
                    float v10 = fmaxf(acc[mt][nt][2] + b0, 0.f);
                    float v11 = fmaxf(acc[mt][nt][3] + b1, 0.f);
                    if (gr0 == g0) { sumA[nt * 2] += v00; sumA[nt * 2 + 1] += v01; }
                    else if (gr0 > g0) { sumB[nt * 2] += v00; sumB[nt * 2 + 1] += v01; }
                    if (gr1 == g0) { sumA[nt * 2] += v10; sumA[nt * 2 + 1] += v11; }
                    else if (gr1 > g0) { sumB[nt * 2] += v10; sumB[nt * 2 + 1] += v11; }
                }
            }
#pragma unroll
            for (int k = 0; k < 16; k++) {
#pragma unroll
                for (int off = 4; off <= 16; off <<= 1) {
                    sumA[k] += __shfl_xor_sync(0xffffffffu, sumA[k], off);
                    sumB[k] += __shfl_xor_sync(0xffffffffu, sumB[k], off);
                }
            }
            if (g == 0) {
#pragma unroll
                for (int nt = 0; nt < 8; nt++) {
                    int col = warpN * 64 + nt * 8 + 2 * c;
                    atomicAdd(&g_pooled[(size_t)g0 * HID + col], sumA[nt * 2]);
                    atomicAdd(&g_pooled[(size_t)g0 * HID + col + 1], sumA[nt * 2 + 1]);
                    if (g1 != g0) {
                        atomicAdd(&g_pooled[(size_t)g1 * HID + col], sumB[nt * 2]);
                        atomicAdd(&g_pooled[(size_t)g1 * HID + col + 1], sumB[nt * 2 + 1]);
                    }
                }
            }
        } else {
#pragma unroll
            for (int mt = 0; mt < 2; mt++) {
                int r0 = m0 + warpM * 32 + mt * 16 + g;
                int r1 = r0 + 8;
#pragma unroll
                for (int nt = 0; nt < 8; nt++) {
                    int col = warpN * 64 + nt * 8 + 2 * c;
                    float b0 = bias[col], b1 = bias[col + 1];
                    float v00 = fmaxf(acc[mt][nt][0] + b0, 0.f);
                    float v01 = fmaxf(acc[mt][nt][1] + b1, 0.f);
                    float v10 = fmaxf(acc[mt][nt][2] + b0, 0.f);
                    float v11 = fmaxf(acc[mt][nt][3] + b1, 0.f);
                    if (r0 < NN) {
                        float* p = g_pooled + (size_t)getidx(batch, r0) * HID + col;
                        atomicAdd(p, v00);
                        atomicAdd(p + 1, v01);
                    }
                    if (r1 < NN) {
                        float* p = g_pooled + (size_t)getidx(batch, r1) * HID + col;
                        atomicAdd(p, v10);
                        atomicAdd(p + 1, v11);
                    }
                }
            }
        }
    } else {
#pragma unroll
        for (int mt = 0; mt < 2; mt++) {
            int r0 = m0 + warpM * 32 + mt * 16 + g;
            int r1 = r0 + 8;
#pragma unroll
            for (int nt = 0; nt < 8; nt++) {
                int col = warpN * 64 + nt * 8 + 2 * c;
                float b0 = bias[col], b1 = bias[col + 1];
                float v00 = fmaxf(acc[mt][nt][0] + b0, 0.f);
                float v01 = fmaxf(acc[mt][nt][1] + b1, 0.f);
                float v10 = fmaxf(acc[mt][nt][2] + b0, 0.f);
                float v11 = fmaxf(acc[mt][nt][3] + b1, 0.f);
                if (r0 < NN) *(float2*)(out + (size_t)r0 * HID + col) = make_float2(v00, v01);
                if (r1 < NN) *(float2*)(out + (size_t)r1 * HID + col) = make_float2(v10, v11);
            }
        }
    }
}

__global__ void __launch_bounds__(256) tc_gemm_l1(
    const float* __restrict__ x, const float* __restrict__ bias) {
    tc_gemm_body<2 * IN_CH, false>(g_agg1, x, g_Wh1, g_Wl1, bias, g_h1, nullptr);
}

__global__ void __launch_bounds__(256) tc_gemm_l2(
    const float* __restrict__ bias, const void* __restrict__ batch) {
    tc_gemm_body<2 * HID, true>(g_agg2, g_h1, g_Wh2, g_Wl2, bias, nullptr, batch);
}

// ---------------- finalize: per-graph mean, Wout, log_softmax ----------------
__global__ void __launch_bounds__(256) finalize(const void* __restrict__ batch,
                                                const float* __restrict__ Wout,
                                                const float* __restrict__ bout,
                                                float* __restrict__ outp) {
    int g = threadIdx.x;
    auto lower_bound = [&](int v) {
        int lo = 0, hi = NN;
        while (lo < hi) {
            int mid = (lo + hi) >> 1;
            if (getidx(batch, mid) < v) lo = mid + 1; else hi = mid;
        }
        return lo;
    };
    int cnt = lower_bound(g + 1) - lower_bound(g);
    float inv = 1.0f / fmaxf((float)cnt, 1.0f);
    float l0 = bout[0], l1 = bout[1];
    for (int c = 0; c < HID; c++) {
        float p = g_pooled[(size_t)g * HID + c] * inv;
        l0 += p * Wout[c];
        l1 += p * Wout[HID + c];
    }
    float m = fmaxf(l0, l1);
    float lse = m + logf(expf(l0 - m) + expf(l1 - m));
    outp[g * 2 + 0] = l0 - lse;
    outp[g * 2 + 1] = l1 - lse;
}

// ---------------- launch ----------------
extern "C" void kernel_launch(void* const* d_in, const int* in_sizes, int n_in,
                              void* d_out, int out_size) {
    const float* x = (const float*)d_in[0];
    const void* ei = d_in[1];
    const void* batch = d_in[2];
    const float* Wl1 = (const float*)d_in[3];
    const float* bl1 = (const float*)d_in[4];
    const float* Wr1 = (const float*)d_in[5];
    const float* Wl2 = (const float*)d_in[6];
    const float* bl2 = (const float*)d_in[7];
    const float* Wr2 = (const float*)d_in[8];
    const float* Wout = (const float*)d_in[9];
    const float* bout = (const float*)d_in[10];
    float* out = (float*)d_out;

    int gemm_blocks = (NN + 127) / 128;

    build_csr<<<CSR_BLOCKS, 256>>>((const unsigned long long*)ei, ei, Wl1, Wr1, Wl2, Wr2);
    gather1<<<(NN * 16 + 255) / 256, 256>>>((const float4*)x);
    tc_gemm_l1<<<gemm_blocks, 256>>>(x, bl1);
    gather2<<<(NN * 32 + 255) / 256, 256>>>();
    tc_gemm_l2<<<gemm_blocks, 256>>>(bl2, batch);
    finalize<<<1, 256>>>(batch, Wout, bout, out);
}

// round 16
// speedup vs baseline: 1.0223x; 1.0223x over previous
#include <cuda_runtime.h>
#include <math.h>

#define NN 100000
#define NE 1000000
#define IN_CH 64
#define HID 128
#define NG 256

#define SCAN_BLOCKS 128
#define SCAN_CH ((NN + SCAN_BLOCKS - 1) / SCAN_BLOCKS)   // 782

// ---------------- scratch (device globals; no allocation) ----------------
__device__ int g_idx64;              // 1 if indices are int64, 0 if int32
__device__ int g_cnt[NN];
__device__ int g_row[NN];
__device__ int g_cur[NN];
__device__ float g_invdeg[NN];
__device__ int g_srcs[NE];
__device__ int g_blocksum[SCAN_BLOCKS];
__device__ __align__(16) float g_agg1[NN * IN_CH];   // 25.6 MB
__device__ __align__(16) float g_agg2[NN * HID];     // 51.2 MB
__device__ __align__(16) float g_h1[NN * HID];       // 51.2 MB
__device__ __align__(16) unsigned g_xbf[NN * IN_CH / 2];   // 12.8 MB bf16x2 mirror of x
__device__ __align__(16) unsigned g_h1bf[NN * HID / 2];    // 25.6 MB bf16x2 mirror of h1
__device__ float g_pooled[NG * HID];
// pre-split weights: packed bf16x2 pairs along k, [outch][K/2]
__device__ __align__(16) unsigned g_Wh1[HID * IN_CH];    // K=128 -> 64 pairs
__device__ __align__(16) unsigned g_Wl1[HID * IN_CH];
__device__ __align__(16) unsigned g_Wh2[HID * HID];      // K=256 -> 128 pairs
__device__ __align__(16) unsigned g_Wl2[HID * HID];

// index accessor honoring detected dtype
__device__ __forceinline__ int getidx(const void* p, long long i) {
    if (g_idx64) return (int)((const long long*)p)[i];
    return ((const int*)p)[i];
}

// ---------------- bf16 helpers ----------------
__device__ __forceinline__ unsigned pack_bf16x2(float lo, float hi) {
    unsigned r;
    asm("cvt.rn.bf16x2.f32 %0, %1, %2;" : "=r"(r) : "f"(hi), "f"(lo));
    return r;
}

// unpack bf16x2 word -> (low-channel, high-channel) floats
__device__ __forceinline__ void bf2f(unsigned w, float& a, float& b) {
    a = __uint_as_float(w << 16);
    b = __uint_as_float(w & 0xffff0000u);
}

__device__ __forceinline__ void mma_bf16(float* c, const unsigned* a, const unsigned* b) {
    asm volatile(
        "mma.sync.aligned.m16n8k16.row.col.f32.bf16.bf16.f32 "
        "{%0,%1,%2,%3},{%4,%5,%6,%7},{%8,%9},{%0,%1,%2,%3};"
        : "+f"(c[0]), "+f"(c[1]), "+f"(c[2]), "+f"(c[3])
        : "r"(a[0]), "r"(a[1]), "r"(a[2]), "r"(a[3]), "r"(b[0]), "r"(b[1]));
}

__device__ __forceinline__ void ldsm_x4(unsigned& r0, unsigned& r1, unsigned& r2, unsigned& r3,
                                        unsigned addr) {
    asm volatile("ldmatrix.sync.aligned.m8n8.x4.shared.b16 {%0,%1,%2,%3}, [%4];"
                 : "=r"(r0), "=r"(r1), "=r"(r2), "=r"(r3) : "r"(addr));
}

__device__ __forceinline__ void ldsm_x2(unsigned& r0, unsigned& r1, unsigned addr) {
    asm volatile("ldmatrix.sync.aligned.m8n8.x2.shared.b16 {%0,%1}, [%2];"
                 : "=r"(r0), "=r"(r1) : "r"(addr));
}

// convert 8 consecutive floats into 4 packed hi-words + 4 packed lo-words
__device__ __forceinline__ void split_bf16_8(const float* v, unsigned* hp, unsigned* lp) {
#pragma unroll
    for (int j = 0; j < 4; j++) {
        float a0 = v[2 * j], a1 = v[2 * j + 1];
        unsigned h = pack_bf16x2(a0, a1);
        float h0 = __uint_as_float(h << 16);
        float h1 = __uint_as_float(h & 0xffff0000u);
        hp[j] = h;
        lp[j] = pack_bf16x2(a0 - h0, a1 - h1);
    }
}

// ---------------- init: dtype probe + zero + weight split + x->bf16 mirror ----------------
__global__ void init_all(const unsigned long long* __restrict__ ei,
                         const float* __restrict__ x,
                         const float* __restrict__ Wl1, const float* __restrict__ Wr1,
                         const float* __restrict__ Wl2, const float* __restrict__ Wr2) {
    if (blockIdx.x == 0 && threadIdx.x == 0) {
        int is64 = 1;
        for (int i = 0; i < 16; i++)
            if (ei[i] >> 32) is64 = 0;
        g_idx64 = is64;
    }
    int i = blockIdx.x * blockDim.x + threadIdx.x;
    int stride = gridDim.x * blockDim.x;
    for (int j = i; j < NN; j += stride) g_cnt[j] = 0;
    for (int j = i; j < NG * HID; j += stride) g_pooled[j] = 0.f;

    // x -> packed bf16x2 mirror
    const int XP = NN * IN_CH / 2;
    const float2* x2 = (const float2*)x;
    for (int j = i; j < XP; j += stride) {
        float2 v = x2[j];
        g_xbf[j] = pack_bf16x2(v.x, v.y);
    }

    const int P1 = HID * IN_CH;          // layer1 pairs (128*64)
    const int P2 = HID * HID;            // layer2 pairs (128*128)
    for (int idx = i; idx < P1 + P2; idx += stride) {
        if (idx < P1) {
            const int PPR = IN_CH;
            int row = idx / PPR, p = idx % PPR;
            int k0 = 2 * p;
            const int KH = IN_CH;
            float v0 = (k0 < KH) ? Wl1[row * KH + k0] : Wr1[row * KH + k0 - KH];
            float v1 = (k0 < KH) ? Wl1[row * KH + k0 + 1] : Wr1[row * KH + k0 + 1 - KH];
            unsigned h = pack_bf16x2(v0, v1);
            float h0 = __uint_as_float(h << 16);
            float h1 = __uint_as_float(h & 0xffff0000u);
            g_Wh1[idx] = h;
            g_Wl1[idx] = pack_bf16x2(v0 - h0, v1 - h1);
        } else {
            int j = idx - P1;
            const int PPR = HID;
            int row = j / PPR, p = j % PPR;
            int k0 = 2 * p;
            const int KH = HID;
            float v0 = (k0 < KH) ? Wl2[row * KH + k0] : Wr2[row * KH + k0 - KH];
            float v1 = (k0 < KH) ? Wl2[row * KH + k0 + 1] : Wr2[row * KH + k0 + 1 - KH];
            unsigned h = pack_bf16x2(v0, v1);
            float h0 = __uint_as_float(h << 16);
            float h1 = __uint_as_float(h & 0xffff0000u);
            g_Wh2[j] = h;
            g_Wl2[j] = pack_bf16x2(v0 - h0, v1 - h1);
        }
    }
}

// ---------------- histogram of dst degrees ----------------
__global__ void __launch_bounds__(256) hist(const void* __restrict__ ei) {
    int e = blockIdx.x * blockDim.x + threadIdx.x;
    if (e >= NE) return;
    int dst = getidx(ei, NE + e);
    atomicAdd(&g_cnt[dst], 1);
}

// ---------------- 2-phase scan ----------------
__global__ void __launch_bounds__(256) scan_p1() {
    __shared__ int sb[256];
    int b = blockIdx.x, t = threadIdx.x;
    int base = b * SCAN_CH;
    int end = min(base + SCAN_CH, NN);
    int s = 0;
    for (int idx = base + t; idx < end; idx += 256) s += g_cnt[idx];
    sb[t] = s;
    __syncthreads();
    for (int off = 128; off > 0; off >>= 1) {
        if (t < off) sb[t] += sb[t + off];
        __syncthreads();
    }
    if (t == 0) g_blocksum[b] = sb[0];
}

__global__ void __launch_bounds__(256) scan_p3() {
    __shared__ int sb[256];
    __shared__ int s_off;
    int b = blockIdx.x, t = threadIdx.x;
    int base = b * SCAN_CH;
    int end = min(base + SCAN_CH, NN);
    sb[t] = (t < b && t < SCAN_BLOCKS) ? g_blocksum[t] : 0;
    __syncthreads();
    for (int off = 128; off > 0; off >>= 1) {
        if (t < off) sb[t] += sb[t + off];
        __syncthreads();
    }
    if (t == 0) s_off = sb[0];
    __syncthreads();
    for (int tile = base; tile < end; tile += 256) {
        int idx = tile + t;
        int c = (idx < end) ? g_cnt[idx] : 0;
        sb[t] = c;
        __syncthreads();
        for (int off = 1; off < 256; off <<= 1) {
            int u = (t >= off) ? sb[t - off] : 0;
            __syncthreads();
            sb[t] += u;
            __syncthreads();
        }
        int incl = sb[t];
        int excl = incl - c;
        if (idx < end) {
            int r = s_off + excl;
            g_row[idx] = r;
            g_cur[idx] = r;
            g_invdeg[idx] = 1.0f / fmaxf((float)c, 1.0f);
        }
        __syncthreads();
        if (t == 255) s_off += sb[255];
        __syncthreads();
    }
}

// ---------------- fill CSR src lists ----------------
__global__ void __launch_bounds__(256) fill_csr(const void* __restrict__ ei) {
    int e = blockIdx.x * blockDim.x + threadIdx.x;
    if (e >= NE) return;
    int dst = getidx(ei, NE + e);
    int src = getidx(ei, e);
    int pos = atomicAdd(&g_cur[dst], 1);
    g_srcs[pos] = src;
}

// accumulate 8 channels from a packed uint4
#define ACC8(v)                                                   \
    do {                                                          \
        float _a, _b;                                             \
        bf2f((v).x, _a, _b); acc[0] += _a; acc[1] += _b;          \
        bf2f((v).y, _a, _b); acc[2] += _a; acc[3] += _b;          \
        bf2f((v).z, _a, _b); acc[4] += _a; acc[5] += _b;          \
        bf2f((v).w, _a, _b); acc[6] += _a; acc[7] += _b;          \
    } while (0)

// ---------------- gather-mean layer 1 (bf16 reads): 8 threads/node ----------------
__global__ void __launch_bounds__(256) gather1() {
    unsigned t = blockIdx.x * blockDim.x + threadIdx.x;
    unsigned n = t >> 3, q = t & 7;          // 8 uint4 per 64-ch bf16 row
    if (n >= NN) return;
    int start = g_row[n];
    int cnt = g_cnt[n];
    float inv = g_invdeg[n];
    const uint4* xb = (const uint4*)g_xbf;
    float acc[8];
#pragma unroll
    for (int i = 0; i < 8; i++) acc[i] = 0.f;
    int j = 0;
    for (; j + 3 < cnt; j += 4) {
        int s0 = g_srcs[start + j];
        int s1 = g_srcs[start + j + 1];
        int s2 = g_srcs[start + j + 2];
        int s3 = g_srcs[start + j + 3];
        uint4 v0 = xb[(size_t)s0 * 8 + q];
        uint4 v1 = xb[(size_t)s1 * 8 + q];
        uint4 v2 = xb[(size_t)s2 * 8 + q];
        uint4 v3 = xb[(size_t)s3 * 8 + q];
        ACC8(v0); ACC8(v1); ACC8(v2); ACC8(v3);
    }
    for (; j < cnt; j++) {
        int s = g_srcs[start + j];
        uint4 v = xb[(size_t)s * 8 + q];
        ACC8(v);
    }
    float4* out = (float4*)g_agg1;
    out[(size_t)n * 16 + q * 2] =
        make_float4(acc[0] * inv, acc[1] * inv, acc[2] * inv, acc[3] * inv);
    out[(size_t)n * 16 + q * 2 + 1] =
        make_float4(acc[4] * inv, acc[5] * inv, acc[6] * inv, acc[7] * inv);
}

// ---------------- gather-mean layer 2 (bf16 reads): 16 threads/node ----------------
__global__ void __launch_bounds__(256) gather2() {
    unsigned t = blockIdx.x * blockDim.x + threadIdx.x;
    unsigned n = t >> 4, q = t & 15;         // 16 uint4 per 128-ch bf16 row
    if (n >= NN) return;
    int start = g_row[n];
    int cnt = g_cnt[n];
    float inv = g_invdeg[n];
    const uint4* hb = (const uint4*)g_h1bf;
    float acc[8];
#pragma unroll
    for (int i = 0; i < 8; i++) acc[i] = 0.f;
    int j = 0;
    for (; j + 3 < cnt; j += 4) {
        int s0 = g_srcs[start + j];
        int s1 = g_srcs[start + j + 1];
        int s2 = g_srcs[start + j + 2];
        int s3 = g_srcs[start + j + 3];
        uint4 v0 = hb[(size_t)s0 * 16 + q];
        uint4 v1 = hb[(size_t)s1 * 16 + q];
        uint4 v2 = hb[(size_t)s2 * 16 + q];
        uint4 v3 = hb[(size_t)s3 * 16 + q];
        ACC8(v0); ACC8(v1); ACC8(v2); ACC8(v3);
    }
    for (; j < cnt; j++) {
        int s = g_srcs[start + j];
        uint4 v = hb[(size_t)s * 16 + q];
        ACC8(v);
    }
    float4* out = (float4*)g_agg2;
    out[(size_t)n * 32 + q * 2] =
        make_float4(acc[0] * inv, acc[1] * inv, acc[2] * inv, acc[3] * inv);
    out[(size_t)n * 32 + q * 2 + 1] =
        make_float4(acc[4] * inv, acc[5] * inv, acc[6] * inv, acc[7] * inv);
}

// ---------------- tensor-core fused SAGE GEMM (3xBF16 m16n8k16 + ldmatrix) ----------------
// Single 24 KB smem buffer (occupancy-sensitive: do NOT double-buffer).
// WRITE_BF: also store result as packed bf16x2 into g_h1bf (for gather2).
template <int K, bool DO_POOL, bool WRITE_BF>
__device__ __forceinline__ void tc_gemm_body(
    const float* __restrict__ agg, const float* __restrict__ feat,
    const unsigned* __restrict__ Wh, const unsigned* __restrict__ Wl,
    const float* __restrict__ bias, float* __restrict__ out,
    const void* __restrict__ batch) {
    constexpr int KH = K / 2;
    constexpr int PPR = K / 2;           // weight pairs per row
    __shared__ unsigned Ah[128][12], Al[128][12];   // [row][kpair], 48B stride
    __shared__ unsigned Bh[128][12], Bl[128][12];   // [outch][kpair]

    int tid = threadIdx.x;
    int lane = tid & 31, wid = tid >> 5;
    int warpM = wid & 3, warpN = wid >> 2;
    int g = lane >> 2, c = lane & 3;
    int m0 = blockIdx.x * 128;

    int lrow = tid >> 1;             // 0..127
    int lhalf = (tid & 1) * 8;       // float offset 0 or 8
    int lkp = (tid & 1) * 4;         // kpair offset 0 or 4

    unsigned AhB = (unsigned)__cvta_generic_to_shared(&Ah[0][0]);
    unsigned AlB = (unsigned)__cvta_generic_to_shared(&Al[0][0]);
    unsigned BhB = (unsigned)__cvta_generic_to_shared(&Bh[0][0]);
    unsigned BlB = (unsigned)__cvta_generic_to_shared(&Bl[0][0]);
    int arow = (lane & 7) + (lane & 8);
    unsigned acol = (lane & 16) ? 16u : 0u;
    unsigned aoff0 = (unsigned)(warpM * 32 + arow) * 48u + acol;
    unsigned aoff1 = aoff0 + 16u * 48u;
    unsigned boff = (unsigned)(warpN * 64 + (lane & 7)) * 48u + ((lane & 8) ? 16u : 0u);

    float acc[2][8][4];
#pragma unroll
    for (int mt = 0; mt < 2; mt++)
#pragma unroll
        for (int nt = 0; nt < 8; nt++)
#pragma unroll
            for (int i = 0; i < 4; i++) acc[mt][nt][i] = 0.f;

    int node_l = m0 + lrow;
    bool av = node_l < NN;

    float a_reg[8];
    uint4 wh_reg, wl_reg;
    {
        int kg = lhalf;
        float4 v0 = make_float4(0.f, 0.f, 0.f, 0.f), v1 = v0;
        if (av) {
            const float* base = (kg < KH) ? (agg + (size_t)node_l * KH + kg)
                                          : (feat + (size_t)node_l * KH + (kg - KH));
            v0 = *(const float4*)base;
            v1 = *(const float4*)(base + 4);
        }
        a_reg[0] = v0.x; a_reg[1] = v0.y; a_reg[2] = v0.z; a_reg[3] = v0.w;
        a_reg[4] = v1.x; a_reg[5] = v1.y; a_reg[6] = v1.z; a_reg[7] = v1.w;
        wh_reg = *(const uint4*)(Wh + (size_t)lrow * PPR + lkp);
        wl_reg = *(const uint4*)(Wl + (size_t)lrow * PPR + lkp);
    }

    for (int kk = 0; kk < K; kk += 16) {
        {
            unsigned hp[4], lp[4];
            split_bf16_8(a_reg, hp, lp);
            *(uint4*)&Ah[lrow][lkp] = make_uint4(hp[0], hp[1], hp[2], hp[3]);
            *(uint4*)&Al[lrow][lkp] = make_uint4(lp[0], lp[1], lp[2], lp[3]);
            *(uint4*)&Bh[lrow][lkp] = wh_reg;
            *(uint4*)&Bl[lrow][lkp] = wl_reg;
        }
        __syncthreads();

        if (kk + 16 < K) {
            int kg = kk + 16 + lhalf;
            float4 v0 = make_float4(0.f, 0.f, 0.f, 0.f), v1 = v0;
            if (av) {
                const float* base = (kg < KH) ? (agg + (size_t)node_l * KH + kg)
                                              : (feat + (size_t)node_l * KH + (kg - KH));
                v0 = *(const float4*)base;
                v1 = *(const float4*)(base + 4);
            }
            a_reg[0] = v0.x; a_reg[1] = v0.y; a_reg[2] = v0.z; a_reg[3] = v0.w;
            a_reg[4] = v1.x; a_reg[5] = v1.y; a_reg[6] = v1.z; a_reg[7] = v1.w;
            int pbase = (kk + 16) / 2 + lkp;
            wh_reg = *(const uint4*)(Wh + (size_t)lrow * PPR + pbase);
            wl_reg = *(const uint4*)(Wl + (size_t)lrow * PPR + pbase);
        }

        {
            unsigned ah[2][4], al[2][4];
            ldsm_x4(ah[0][0], ah[0][1], ah[0][2], ah[0][3], AhB + aoff0);
            ldsm_x4(ah[1][0], ah[1][1], ah[1][2], ah[1][3], AhB + aoff1);
            ldsm_x4(al[0][0], al[0][1], al[0][2], al[0][3], AlB + aoff0);
            ldsm_x4(al[1][0], al[1][1], al[1][2], al[1][3], AlB + aoff1);
#pragma unroll
            for (int nt = 0; nt < 8; nt++) {
                unsigned bh[2], bl[2];
                ldsm_x2(bh[0], bh[1], BhB + boff + nt * 384u);
                ldsm_x2(bl[0], bl[1], BlB + boff + nt * 384u);
#pragma unroll
                for (int mt = 0; mt < 2; mt++) {
                    mma_bf16(acc[mt][nt], ah[mt], bh);   // hi*hi
                    mma_bf16(acc[mt][nt], ah[mt], bl);   // hi*lo
                    mma_bf16(acc[mt][nt], al[mt], bh);   // lo*hi
                }
            }
        }
        __syncthreads();
    }

    // ---- epilogue ----
    if (DO_POOL) {
        int lastrow = min(m0 + 127, NN - 1);
        int g0 = getidx(batch, m0);
        int g1 = getidx(batch, lastrow);
        if (g1 - g0 <= 1) {
            float sumA[16], sumB[16];
#pragma unroll
            for (int k = 0; k < 16; k++) { sumA[k] = 0.f; sumB[k] = 0.f; }
#pragma unroll
            for (int mt = 0; mt < 2; mt++) {
                int r0 = m0 + warpM * 32 + mt * 16 + g;
                int r1 = r0 + 8;
                int gr0 = (r0 < NN) ? getidx(batch, r0) : -1;
                int gr1 = (r1 < NN) ? getidx(batch, r1) : -1;
#pragma unroll
                for (int nt = 0; nt < 8; nt++) {
                    int col = warpN * 64 + nt * 8 + 2 * c;
                    float b0 = bias[col], b1 = bias[col + 1];
                    float v00 = fmaxf(acc[mt][nt][0] + b0, 0.f);
                    float v01 = fmaxf(acc[mt][nt][1] + b1, 0.f);
                    float v10 = fmaxf(acc[mt][nt][2] + b0, 0.f);
                    float v11 = fmaxf(acc[mt][nt][3] + b1, 0.f);
                    if (gr0 == g0) { sumA[nt * 2] += v00; sumA[nt * 2 + 1] += v01; }
                    else if (gr0 > g0) { sumB[nt * 2] += v00; sumB[nt * 2 + 1] += v01; }
                    if (gr1 == g0) { sumA[nt * 2] += v10; sumA[nt * 2 + 1] += v11; }
                    else if (gr1 > g0) { sumB[nt * 2] += v10; sumB[nt * 2 + 1] += v11; }
                }
            }
#pragma unroll
            for (int k = 0; k < 16; k++) {
#pragma unroll
                for (int off = 4; off <= 16; off <<= 1) {
                    sumA[k] += __shfl_xor_sync(0xffffffffu, sumA[k], off);
                    sumB[k] += __shfl_xor_sync(0xffffffffu, sumB[k], off);
                }
            }
            if (g == 0) {
#pragma unroll
                for (int nt = 0; nt < 8; nt++) {
                    int col = warpN * 64 + nt * 8 + 2 * c;
                    atomicAdd(&g_pooled[(size_t)g0 * HID + col], sumA[nt * 2]);
                    atomicAdd(&g_pooled[(size_t)g0 * HID + col + 1], sumA[nt * 2 + 1]);
                    if (g1 != g0) {
                        atomicAdd(&g_pooled[(size_t)g1 * HID + col], sumB[nt * 2]);
                        atomicAdd(&g_pooled[(size_t)g1 * HID + col + 1], sumB[nt * 2 + 1]);
                    }
                }
            }
        } else {
#pragma unroll
            for (int mt = 0; mt < 2; mt++) {
                int r0 = m0 + warpM * 32 + mt * 16 + g;
                int r1 = r0 + 8;
#pragma unroll
                for (int nt = 0; nt < 8; nt++) {
                    int col = warpN * 64 + nt * 8 + 2 * c;
                    float b0 = bias[col], b1 = bias[col + 1];
                    float v00 = fmaxf(acc[mt][nt][0] + b0, 0.f);
                    float v01 = fmaxf(acc[mt][nt][1] + b1, 0.f);
                    float v10 = fmaxf(acc[mt][nt][2] + b0, 0.f);
                    float v11 = fmaxf(acc[mt][nt][3] + b1, 0.f);
                    if (r0 < NN) {
                        float* p = g_pooled + (size_t)getidx(batch, r0) * HID + col;
                        atomicAdd(p, v00);
                        atomicAdd(p + 1, v01);
                    }
                    if (r1 < NN) {
                        float* p = g_pooled + (size_t)getidx(batch, r1) * HID + col;
                        atomicAdd(p, v10);
                        atomicAdd(p + 1, v11);
                    }
                }
            }
        }
    } else {
#pragma unroll
        for (int mt = 0; mt < 2; mt++) {
            int r0 = m0 + warpM * 32 + mt * 16 + g;
            int r1 = r0 + 8;
#pragma unroll
            for (int nt = 0; nt < 8; nt++) {
                int col = warpN * 64 + nt * 8 + 2 * c;
                float b0 = bias[col], b1 = bias[col + 1];
                float v00 = fmaxf(acc[mt][nt][0] + b0, 0.f);
                float v01 = fmaxf(acc[mt][nt][1] + b1, 0.f);
                float v10 = fmaxf(acc[mt][nt][2] + b0, 0.f);
                float v11 = fmaxf(acc[mt][nt][3] + b1, 0.f);
                if (r0 < NN) {
                    *(float2*)(out + (size_t)r0 * HID + col) = make_float2(v00, v01);
                    if (WRITE_BF)
                        g_h1bf[(size_t)r0 * (HID / 2) + (col >> 1)] = pack_bf16x2(v00, v01);
                }
                if (r1 < NN) {
                    *(float2*)(out + (size_t)r1 * HID + col) = make_float2(v10, v11);
                    if (WRITE_BF)
                        g_h1bf[(size_t)r1 * (HID / 2) + (col >> 1)] = pack_bf16x2(v10, v11);
                }
            }
        }
    }
}

__global__ void __launch_bounds__(256) tc_gemm_l1(
    const float* __restrict__ x, const float* __restrict__ bias) {
    tc_gemm_body<2 * IN_CH, false, true>(g_agg1, x, g_Wh1, g_Wl1, bias, g_h1, nullptr);
}

__global__ void __launch_bounds__(256) tc_gemm_l2(
    const float* __restrict__ bias, const void* __restrict__ batch) {
    tc_gemm_body<2 * HID, true, false>(g_agg2, g_h1, g_Wh2, g_Wl2, bias, nullptr, batch);
}

// ---------------- finalize: per-graph mean, Wout, log_softmax ----------------
__global__ void __launch_bounds__(256) finalize(const void* __restrict__ batch,
                                                const float* __restrict__ Wout,
                                                const float* __restrict__ bout,
                                                float* __restrict__ outp) {
    int g = threadIdx.x;
    auto lower_bound = [&](int v) {
        int lo = 0, hi = NN;
        while (lo < hi) {
            int mid = (lo + hi) >> 1;
            if (getidx(batch, mid) < v) lo = mid + 1; else hi = mid;
        }
        return lo;
    };
    int cnt = lower_bound(g + 1) - lower_bound(g);
    float inv = 1.0f / fmaxf((float)cnt, 1.0f);
    float l0 = bout[0], l1 = bout[1];
    for (int c = 0; c < HID; c++) {
        float p = g_pooled[(size_t)g * HID + c] * inv;
        l0 += p * Wout[c];
        l1 += p * Wout[HID + c];
    }
    float m = fmaxf(l0, l1);
    float lse = m + logf(expf(l0 - m) + expf(l1 - m));
    outp[g * 2 + 0] = l0 - lse;
    outp[g * 2 + 1] = l1 - lse;
}

// ---------------- launch ----------------
extern "C" void kernel_launch(void* const* d_in, const int* in_sizes, int n_in,
                              void* d_out, int out_size) {
    const float* x = (const float*)d_in[0];
    const void* ei = d_in[1];
    const void* batch = d_in[2];
    const float* Wl1 = (const float*)d_in[3];
    const float* bl1 = (const float*)d_in[4];
    const float* Wr1 = (const float*)d_in[5];
    const float* Wl2 = (const float*)d_in[6];
    const float* bl2 = (const float*)d_in[7];
    const float* Wr2 = (const float*)d_in[8];
    const float* Wout = (const float*)d_in[9];
    const float* bout = (const float*)d_in[10];
    float* out = (float*)d_out;

    int eb = (NE + 255) / 256;
    int gemm_blocks = (NN + 127) / 128;

    init_all<<<256, 256>>>((const unsigned long long*)ei, x, Wl1, Wr1, Wl2, Wr2);
    hist<<<eb, 256>>>(ei);
    scan_p1<<<SCAN_BLOCKS, 256>>>();
    scan_p3<<<SCAN_BLOCKS, 256>>>();
    fill_csr<<<eb, 256>>>(ei);

    gather1<<<(NN * 8 + 255) / 256, 256>>>();
    tc_gemm_l1<<<gemm_blocks, 256>>>(x, bl1);
    gather2<<<(NN * 16 + 255) / 256, 256>>>();
    tc_gemm_l2<<<gemm_blocks, 256>>>(bl2, batch);
    finalize<<<1, 256>>>(batch, Wout, bout, out);
}